// round 17
// baseline (speedup 1.0000x reference)
#include <cuda_runtime.h>
#include <cuda_fp16.h>
#include <math.h>
#include <stdint.h>

#define BATCH   4
#define SEQ     2048
#define EMB     1024
#define KVD     256
#define HEADS   16
#define HDIM    64
#define MTOT    (BATCH*SEQ)   // 8192
#define KWW     (EMB/2)       // 512 words: K-dim words for every GEMM

// -------- scratch (uint32 words holding fp16x2) --------
__device__ uint32_t g_xa [(size_t)MTOT * EMB / 2];   // x fp16, then attn out fp16
__device__ uint32_t g_q  [(size_t)MTOT * EMB / 2];
__device__ uint32_t g_k  [(size_t)MTOT * KVD / 2];
__device__ uint32_t g_v  [(size_t)MTOT * KVD / 2];
__device__ uint32_t g_wq [(size_t)EMB * KWW];        // n-major k-pair words
__device__ uint32_t g_wk [(size_t)KVD * KWW];
__device__ uint32_t g_wv [(size_t)KVD * KWW];
__device__ uint32_t g_wo [(size_t)EMB * KWW];

// ---------------- helpers ----------------
__device__ __forceinline__ uint32_t h2(float lo, float hi) {
    uint32_t r;
    asm("cvt.rn.f16x2.f32 %0, %1, %2;" : "=r"(r) : "f"(hi), "f"(lo));
    return r;
}
__device__ __forceinline__ uint32_t ex2h2(uint32_t x) {
    uint32_t r;
    asm("ex2.approx.f16x2 %0, %1;" : "=r"(r) : "r"(x));
    return r;
}
__device__ __forceinline__ uint32_t smem_u32(const void* p) {
    uint32_t a;
    asm("{ .reg .u64 t; cvta.to.shared.u64 t, %1; cvt.u32.u64 %0, t; }"
        : "=r"(a) : "l"(p));
    return a;
}
__device__ __forceinline__ void cpa16(uint32_t dst, const void* src) {
    asm volatile("cp.async.cg.shared.global [%0], [%1], 16;"
                 :: "r"(dst), "l"(src) : "memory");
}
#define CP_COMMIT asm volatile("cp.async.commit_group;" ::: "memory")
#define CP_WAIT0  asm volatile("cp.async.wait_group 0;" ::: "memory")

__device__ __forceinline__ void mma16(float& d0, float& d1, float& d2, float& d3,
                                      uint32_t a0, uint32_t a1, uint32_t a2, uint32_t a3,
                                      uint32_t b0, uint32_t b1) {
    asm volatile(
        "mma.sync.aligned.m16n8k16.row.col.f32.f16.f16.f32 "
        "{%0,%1,%2,%3}, {%4,%5,%6,%7}, {%8,%9}, {%0,%1,%2,%3};"
        : "+f"(d0), "+f"(d1), "+f"(d2), "+f"(d3)
        : "r"(a0), "r"(a1), "r"(a2), "r"(a3), "r"(b0), "r"(b1));
}
__device__ __forceinline__ void ldsm4(uint32_t& r0, uint32_t& r1,
                                      uint32_t& r2, uint32_t& r3, uint32_t addr) {
    asm volatile("ldmatrix.sync.aligned.m8n8.x4.shared.b16 {%0,%1,%2,%3}, [%4];"
                 : "=r"(r0), "=r"(r1), "=r"(r2), "=r"(r3) : "r"(addr));
}
__device__ __forceinline__ void ldsm4t(uint32_t& r0, uint32_t& r1,
                                       uint32_t& r2, uint32_t& r3, uint32_t addr) {
    asm volatile("ldmatrix.sync.aligned.m8n8.x4.trans.shared.b16 {%0,%1,%2,%3}, [%4];"
                 : "=r"(r0), "=r"(r1), "=r"(r2), "=r"(r3) : "r"(addr));
}

// ============================================================================
// prep (merged): blocks [0, UXB) convert x; blocks [UXB, UXB+640) transpose W.
// ============================================================================
#define UX  ((size_t)MTOT*EMB/4)
#define UXB ((unsigned)((UX + 255) / 256))   // 8192 blocks

__global__ void __launch_bounds__(256) prep_kernel(
    uint32_t* __restrict__ xh, const float4* __restrict__ x,
    const float* __restrict__ wq, const float* __restrict__ wk,
    const float* __restrict__ wv, const float* __restrict__ wo,
    uint32_t* __restrict__ wqt, uint32_t* __restrict__ wkt,
    uint32_t* __restrict__ wvt, uint32_t* __restrict__ wot)
{
    if (blockIdx.x < UXB) {
        size_t u = (size_t)blockIdx.x * 256 + threadIdx.x;
        if (u >= UX) return;
        float4 v = x[u];
        xh[2*u]     = h2(v.x, v.y);
        xh[2*u + 1] = h2(v.z, v.w);
        return;
    }
    __shared__ __half S[64][65];
    int b = blockIdx.x - UXB;
    const float* W; uint32_t* Wt; int N, kt, nt;
    if (b < 256)      {           W = wq; Wt = wqt; N = EMB; kt = b >> 4; nt = b & 15; }
    else if (b < 320) { b -= 256; W = wk; Wt = wkt; N = KVD; kt = b >> 2; nt = b & 3;  }
    else if (b < 384) { b -= 320; W = wv; Wt = wvt; N = KVD; kt = b >> 2; nt = b & 3;  }
    else              { b -= 384; W = wo; Wt = wot; N = EMB; kt = b >> 4; nt = b & 15; }
    const int tid = threadIdx.x;

    #pragma unroll
    for (int p = 0; p < 4; p++) {
        int idx = tid + p * 256;
        int r = idx >> 4, c4 = idx & 15;
        float4 v = *(const float4*)(W + (size_t)(kt*64 + r) * N + nt*64 + c4*4);
        S[r][c4*4 + 0] = __float2half_rn(v.x);
        S[r][c4*4 + 1] = __float2half_rn(v.y);
        S[r][c4*4 + 2] = __float2half_rn(v.z);
        S[r][c4*4 + 3] = __float2half_rn(v.w);
    }
    __syncthreads();

    #pragma unroll
    for (int p = 0; p < 8; p++) {
        int kp = tid & 31, n = (tid >> 5) + p * 8;
        uint32_t lo = __half_as_ushort(S[2*kp][n]);
        uint32_t hi = __half_as_ushort(S[2*kp + 1][n]);
        Wt[(size_t)(nt*64 + n) * KWW + kt*32 + kp] = lo | (hi << 16);
    }
}

// ============================================================================
// fp16 GEMM via ldmatrix, K64 per iteration (16 iters, 16 barriers).
// A words [M][512] natural pairs; Wt words [N][512] n-major pairs.
// smem per stage: As [128][36w], Bs [128][36w]; 2 stages = 73728 bytes.
// OUT: 0 = fp32 store, 1 = fp16-pack store, 2 = fp16-pack * qscale.
// ============================================================================
#define GAW (128*36)
#define GEMM_SMEM_BYTES (GAW * 4 * 4)   // 73728

template<int OUT>
__device__ __forceinline__ void gemm_tile(
    const uint32_t* __restrict__ Aw, const uint32_t* __restrict__ Wt,
    const float* __restrict__ bias, void* __restrict__ Cv_,
    int N, int m0, int n0, uint32_t sb)
{
    const int tid  = threadIdx.x;
    const int lane = tid & 31, wid = tid >> 5;
    const int wm = wid & 3, wn = wid >> 2;
    const int g = lane >> 2, t = lane & 3;
    const int l = lane & 7, mq = lane >> 3;

    const int frow = tid >> 1, fh = (tid & 1) * 16;   // fill: 2 thr/row, 4 uint4 each

    const uint32_t sA[2] = { sb,             sb + GAW*4 };
    const uint32_t sB[2] = { sb + 2*GAW*4,   sb + 3*GAW*4 };

    const uint32_t aoff = (uint32_t)(((mq & 1)*8 + l) * 36 + (mq >> 1)*4);
    const uint32_t boff = (uint32_t)(((mq >> 1)*8 + l) * 36 + (mq & 1)*4);

    float acc[2][8][4] = {};

    // prefetch it=0 (K words 0..31)
    {
        const uint32_t* Ab = Aw + (size_t)(m0 + frow) * KWW + fh;
        const uint32_t* Bb = Wt + (size_t)(n0 + frow) * KWW + fh;
        #pragma unroll
        for (int c = 0; c < 4; c++) {
            cpa16(sA[0] + (frow*36 + fh + c*4)*4, Ab + c*4);
            cpa16(sB[0] + (frow*36 + fh + c*4)*4, Bb + c*4);
        }
        CP_COMMIT;
    }

    const int NIT = 16;   // K = 1024 = 16 iters of K64
    for (int it = 0; it < NIT; ++it) {
        CP_WAIT0;
        __syncthreads();

        if (it + 1 < NIT) {
            const int buf = (it + 1) & 1;
            const uint32_t* Ab = Aw + (size_t)(m0 + frow) * KWW + (it + 1) * 32 + fh;
            const uint32_t* Bb = Wt + (size_t)(n0 + frow) * KWW + (it + 1) * 32 + fh;
            #pragma unroll
            for (int c = 0; c < 4; c++) {
                cpa16(sA[buf] + (frow*36 + fh + c*4)*4, Ab + c*4);
                cpa16(sB[buf] + (frow*36 + fh + c*4)*4, Bb + c*4);
            }
            CP_COMMIT;
        }

        const uint32_t aB = sA[it & 1], bB = sB[it & 1];
        #pragma unroll
        for (int kc = 0; kc < 4; ++kc) {
            uint32_t a[2][4], b[8][2];
            #pragma unroll
            for (int mt = 0; mt < 2; mt++)
                ldsm4(a[mt][0], a[mt][1], a[mt][2], a[mt][3],
                      aB + (aoff + (uint32_t)((wm*32 + mt*16)*36 + kc*8))*4);
            #pragma unroll
            for (int j = 0; j < 8; j += 2)
                ldsm4(b[j][0], b[j][1], b[j+1][0], b[j+1][1],
                      bB + (boff + (uint32_t)((wn*64 + j*8)*36 + kc*8))*4);
            #pragma unroll
            for (int mt = 0; mt < 2; mt++)
                #pragma unroll
                for (int j = 0; j < 8; j++)
                    mma16(acc[mt][j][0], acc[mt][j][1], acc[mt][j][2], acc[mt][j][3],
                          a[mt][0], a[mt][1], a[mt][2], a[mt][3], b[j][0], b[j][1]);
        }
    }

    const float qs = 0.125f * 1.44269504088896340736f;
    #pragma unroll
    for (int mt = 0; mt < 2; mt++) {
        int r0 = m0 + wm * 32 + mt * 16 + g;
        #pragma unroll
        for (int j = 0; j < 8; j++) {
            int c0 = n0 + wn * 64 + j * 8 + 2 * t;
            float2 bb = *(const float2*)(bias + c0);
            float o00 = acc[mt][j][0] + bb.x, o01 = acc[mt][j][1] + bb.y;
            float o10 = acc[mt][j][2] + bb.x, o11 = acc[mt][j][3] + bb.y;
            if (OUT == 0) {
                float* C = (float*)Cv_;
                float2 v0 = { o00, o01 }, v1 = { o10, o11 };
                *(float2*)(C + (size_t)r0 * N + c0)       = v0;
                *(float2*)(C + (size_t)(r0 + 8) * N + c0) = v1;
            } else {
                if (OUT == 2) { o00 *= qs; o01 *= qs; o10 *= qs; o11 *= qs; }
                uint32_t* C = (uint32_t*)Cv_;
                int hw = c0 >> 1;
                C[(size_t)r0 * (N>>1) + hw]       = h2(o00, o01);
                C[(size_t)(r0 + 8) * (N>>1) + hw] = h2(o10, o11);
            }
        }
    }
}

__global__ void __launch_bounds__(256, 2) gemm_qkv(
    const uint32_t* __restrict__ xh,
    const uint32_t* __restrict__ Wq, const float* __restrict__ bq, uint32_t* __restrict__ Cq,
    const uint32_t* __restrict__ Wk, const float* __restrict__ bk, uint32_t* __restrict__ Ck,
    const uint32_t* __restrict__ Wv, const float* __restrict__ bv, uint32_t* __restrict__ Cv)
{
    extern __shared__ uint32_t sm[];
    uint32_t sb = smem_u32(sm);
    const int bx = blockIdx.x, m0 = blockIdx.y * 128;
    if (bx < 8) {
        gemm_tile<2>(xh, Wq, bq, Cq, EMB, m0, bx * 128, sb);
    } else {
        const int x2 = bx - 8;
        const bool isV = (x2 >> 1) != 0;
        gemm_tile<1>(xh, isV ? Wv : Wk, isV ? bv : bk, isV ? Cv : Ck,
                     KVD, m0, (x2 & 1) * 128, sb);
    }
}

__global__ void __launch_bounds__(256, 2) gemm_out(
    const uint32_t* __restrict__ Aw, const uint32_t* __restrict__ Wt,
    const float* __restrict__ bias, float* __restrict__ C)
{
    extern __shared__ uint32_t sm[];
    gemm_tile<0>(Aw, Wt, bias, C, EMB, blockIdx.y * 128, blockIdx.x * 128,
                 smem_u32(sm));
}

// ============================================================================
// Flash attention (unchanged from R16 — proven).
// 128 threads (4 warps) = 4 heads x 32 queries, 2 CTAs/SM, split prefetch.
// ============================================================================
#define ATW (64*36)
#define ATTN_SMEM_BYTES (4 * ATW * 4)   // 36864

__global__ void __launch_bounds__(128, 2) attn_mma(
    const uint32_t* __restrict__ q, const uint32_t* __restrict__ k,
    const uint32_t* __restrict__ v, uint32_t* __restrict__ out)
{
    extern __shared__ uint32_t sm[];
    uint32_t* bK[2] = { sm,         sm + 2*ATW };
    uint32_t* bV[2] = { sm + ATW,   sm + 3*ATW };
    const uint32_t sb = smem_u32(sm);
    const uint32_t aK[2] = { sb,           sb + 2*ATW*4 };
    const uint32_t aV[2] = { sb + ATW*4,   sb + 3*ATW*4 };

    const int tid  = threadIdx.x;
    const int lane = tid & 31, w = tid >> 5;
    const int g = lane >> 2, t = lane & 3;
    const int l = lane & 7, mq = lane >> 3;
    const int q0  = blockIdx.x * 32;
    const int grp = blockIdx.y, bat = blockIdx.z;
    const int h   = grp * 4 + w;

    const uint32_t koff = (uint32_t)(((mq >> 1)*8 + l) * 36 + (mq & 1)*4);
    const uint32_t voff = (uint32_t)(((mq & 1)*8 + l) * 36 + (mq >> 1)*4);
    const uint32_t ONES = 0x3C003C00u;

    uint32_t qf[2][4][4];
    #pragma unroll
    for (int s = 0; s < 2; s++) {
        const uint32_t* Qb = q + (size_t)(bat * SEQ + q0 + s*16) * (EMB/2) + h * (HDIM/2);
        #pragma unroll
        for (int kc = 0; kc < 4; kc++) {
            qf[s][kc][0] = Qb[(size_t)g       * (EMB/2) + kc*8 + t];
            qf[s][kc][1] = Qb[(size_t)(g + 8) * (EMB/2) + kc*8 + t];
            qf[s][kc][2] = Qb[(size_t)g       * (EMB/2) + kc*8 + t + 4];
            qf[s][kc][3] = Qb[(size_t)(g + 8) * (EMB/2) + kc*8 + t + 4];
        }
    }

    const uint32_t* Kbase = k + (size_t)(bat * SEQ) * (KVD/2) + grp * (HDIM/2);
    const uint32_t* Vbase = v + (size_t)(bat * SEQ) * (KVD/2) + grp * (HDIM/2);
    const int frow = tid >> 3, fc = tid & 7;

    #pragma unroll
    for (int i = 0; i < 4; i++) {
        int row = frow + 16 * i;
        uint4 uk = *(const uint4*)(Kbase + (size_t)row * (KVD/2) + fc*4);
        uint4 uv = *(const uint4*)(Vbase + (size_t)row * (KVD/2) + fc*4);
        *(uint4*)&bK[0][row*36 + fc*4] = uk;
        *(uint4*)&bV[0][row*36 + fc*4] = uv;
    }
    __syncthreads();

    float ssum[2][4] = {};
    float oacc[2][8][4] = {};

    const int NT = SEQ / 64;
    for (int kt = 0; kt < NT; ++kt) {
        const bool more = (kt + 1 < NT);
        const int buf = kt & 1, nb = (kt + 1) & 1;
        const uint32_t sbK = aK[buf], sbV = aV[buf];

        uint4 nk[4];
        if (more) {
            #pragma unroll
            for (int i = 0; i < 4; i++)
                nk[i] = *(const uint4*)(Kbase +
                        (size_t)((kt+1)*64 + frow + 16*i) * (KVD/2) + fc*4);
        }

        float sc[2][8][4] = {};
        #pragma unroll
        for (int kc = 0; kc < 4; kc++) {
            #pragma unroll
            for (int j = 0; j < 8; j += 2) {
                uint32_t b00, b01, b10, b11;
                ldsm4(b00, b01, b10, b11, sbK + (koff + (uint32_t)(j*8*36 + kc*8))*4);
                #pragma unroll
                for (int s = 0; s < 2; s++) {
                    mma16(sc[s][j][0], sc[s][j][1], sc[s][j][2], sc[s][j][3],
                          qf[s][kc][0], qf[s][kc][1], qf[s][kc][2], qf[s][kc][3],
                          b00, b01);
                    mma16(sc[s][j+1][0], sc[s][j+1][1], sc[s][j+1][2], sc[s][j+1][3],
                          qf[s][kc][0], qf[s][kc][1], qf[s][kc][2], qf[s][kc][3],
                          b10, b11);
                }
            }
        }

        uint4 nv[4];
        if (more) {
            #pragma unroll
            for (int i = 0; i < 4; i++)
                *(uint4*)&bK[nb][(frow + 16*i)*36 + fc*4] = nk[i];
            #pragma unroll
            for (int i = 0; i < 4; i++)
                nv[i] = *(const uint4*)(Vbase +
                        (size_t)((kt+1)*64 + frow + 16*i) * (KVD/2) + fc*4);
        }

        uint32_t p01[2][8], p23[2][8];
        #pragma unroll
        for (int s = 0; s < 2; s++)
            #pragma unroll
            for (int j = 0; j < 8; j++) {
                p01[s][j] = ex2h2(h2(sc[s][j][0], sc[s][j][1]));
                p23[s][j] = ex2h2(h2(sc[s][j][2], sc[s][j][3]));
            }

        #pragma unroll
        for (int kpc = 0; kpc < 4; kpc++) {
            uint32_t a[2][4];
            #pragma unroll
            for (int s = 0; s < 2; s++) {
                a[s][0] = p01[s][2*kpc];   a[s][1] = p23[s][2*kpc];
                a[s][2] = p01[s][2*kpc+1]; a[s][3] = p23[s][2*kpc+1];
                mma16(ssum[s][0], ssum[s][1], ssum[s][2], ssum[s][3],
                      a[s][0], a[s][1], a[s][2], a[s][3], ONES, ONES);
            }
            #pragma unroll
            for (int j = 0; j < 8; j += 2) {
                uint32_t b00, b01, b10, b11;
                ldsm4t(b00, b01, b10, b11,
                       sbV + (voff + (uint32_t)(kpc*16*36 + j*4))*4);
                #pragma unroll
                for (int s = 0; s < 2; s++) {
                    mma16(oacc[s][j][0], oacc[s][j][1], oacc[s][j][2], oacc[s][j][3],
                          a[s][0], a[s][1], a[s][2], a[s][3], b00, b01);
                    mma16(oacc[s][j+1][0], oacc[s][j+1][1], oacc[s][j+1][2], oacc[s][j+1][3],
                          a[s][0], a[s][1], a[s][2], a[s][3], b10, b11);
                }
            }
        }

        if (more) {
            #pragma unroll
            for (int i = 0; i < 4; i++)
                *(uint4*)&bV[nb][(frow + 16*i)*36 + fc*4] = nv[i];
        }
        __syncthreads();
    }

    #pragma unroll
    for (int s = 0; s < 2; s++) {
        float inv0 = 1.0f / ssum[s][0], inv1 = 1.0f / ssum[s][2];
        uint32_t* Ob = out + (size_t)(bat * SEQ + q0 + s*16) * (EMB/2) + h * (HDIM/2);
        #pragma unroll
        for (int j = 0; j < 8; j++) {
            Ob[(size_t)g       * (EMB/2) + j*4 + t] =
                h2(oacc[s][j][0]*inv0, oacc[s][j][1]*inv0);
            Ob[(size_t)(g + 8) * (EMB/2) + j*4 + t] =
                h2(oacc[s][j][2]*inv1, oacc[s][j][3]*inv1);
        }
    }
}

// ============================================================================
extern "C" void kernel_launch(void* const* d_in, const int* in_sizes, int n_in,
                              void* d_out, int out_size)
{
    const float* x  = (const float*)d_in[0];
    const float* Wq = (const float*)d_in[1];
    const float* bq = (const float*)d_in[2];
    const float* Wk = (const float*)d_in[3];
    const float* bk = (const float*)d_in[4];
    const float* Wv = (const float*)d_in[5];
    const float* bv = (const float*)d_in[6];
    const float* Wo = (const float*)d_in[7];
    const float* bo = (const float*)d_in[8];
    float* out = (float*)d_out;

    uint32_t *xa, *qp, *kp, *vp, *wq, *wk, *wv, *wo;
    cudaGetSymbolAddress((void**)&xa, g_xa);
    cudaGetSymbolAddress((void**)&qp, g_q);
    cudaGetSymbolAddress((void**)&kp, g_k);
    cudaGetSymbolAddress((void**)&vp, g_v);
    cudaGetSymbolAddress((void**)&wq, g_wq);
    cudaGetSymbolAddress((void**)&wk, g_wk);
    cudaGetSymbolAddress((void**)&wv, g_wv);
    cudaGetSymbolAddress((void**)&wo, g_wo);

    cudaFuncSetAttribute(gemm_qkv,
                         cudaFuncAttributeMaxDynamicSharedMemorySize, GEMM_SMEM_BYTES);
    cudaFuncSetAttribute(gemm_out,
                         cudaFuncAttributeMaxDynamicSharedMemorySize, GEMM_SMEM_BYTES);
    cudaFuncSetAttribute(attn_mma,
                         cudaFuncAttributeMaxDynamicSharedMemorySize, ATTN_SMEM_BYTES);

    // 1) merged prep: x -> fp16; W -> n-major fp16 k-pair words
    prep_kernel<<<UXB + 640, 256>>>(xa, (const float4*)x,
                                    Wq, Wk, Wv, Wo, wq, wk, wv, wo);

    // 2) fused Q/K/V projections (fp16 outputs; Q has softmax scale folded)
    gemm_qkv<<<dim3(12, MTOT/128), 256, GEMM_SMEM_BYTES>>>(
        xa, wq, bq, qp, wk, bk, kp, wv, bv, vp);

    // 3) fused GQA attention (fp16 output into g_xa), 2 CTAs/SM
    attn_mma<<<dim3(SEQ/32, 4, BATCH), 128, ATTN_SMEM_BYTES>>>(qp, kp, vp, xa);

    // 4) output projection (fp32 out)
    gemm_out<<<dim3(EMB/128, MTOT/128), 256, GEMM_SMEM_BYTES>>>(xa, wo, bo, out);
}